// round 4
// baseline (speedup 1.0000x reference)
#include <cuda_runtime.h>
#include <math.h>

// Batched SIREN MLP: coords (B,N,2) f32, flat_weights (B,921) f32 -> (B,N,1) f32
// 2->20->20->20->1, hidden act sin(20*(Wx+b)), final clip [0,1].
//
// Numerics hypothesis (R4): the reference lowering computes the dot products
// WITHOUT fma contraction — round(mul) then round(add), k ascending, acc from 0
// (XLA emits fmul+fadd; LLVM doesn't contract without fast-math). The network
// amplifies a 1-ulp layer-1 difference by ~2e4, which matches the stable
// 8.4e-3 rel_err seen when using sequential-fma dots. Sine must be (and is)
// correctly rounded — float-float implementation below, abs err ~1e-12.

#define HID 20
#define PSZ 921

__device__ __forceinline__ float sin_cr(float x) {
    // Correctly-rounded float sine for |x| <= ~1600.
    constexpr float  INV_PIO2 = 0.636619772367581343f;
    constexpr float  P1 = 1.57079637050628662109375f;          // float(pi/2)
    constexpr double PIO2 = 1.5707963267948966192313216916398;
    constexpr double D1 = PIO2 - (double)P1;
    constexpr float  P2 = (float)D1;
    constexpr float  P3 = (float)(D1 - (double)P2);

    float kf = rintf(x * INV_PIO2);
    int   q  = (int)kf;

    // r = x - kf*(P1+P2+P3) as float-float (rh, rl), ~exact.
    float ph = kf * P1;
    float pl = fmaf(kf, P1, -ph);
    float s  = x - ph;
    float bb = s - x;
    float er = (x - (s - bb)) + ((-ph) - bb);
    float mh = kf * P2;
    float ml = fmaf(kf, P2, -mh);
    float lo = ((er - pl) - mh) - ml;
    lo = fmaf(-kf, P3, lo);
    float rh = s + lo;
    float rl = (s - rh) + lo;

    float zh = rh * rh;
    float zl = fmaf(2.0f * rh, rl, fmaf(rh, rh, -zh));

    // sin(r) = r + r^3 * P(z), leading coeffs in float-float
    constexpr double c3d = -1.0 / 6.0,  c5d = 1.0 / 120.0;
    constexpr float C3h = (float)c3d, C3l = (float)(c3d - (double)C3h);
    constexpr float C5h = (float)c5d, C5l = (float)(c5d - (double)C5h);
    constexpr float C7  = -1.98412698412698413e-4f;
    constexpr float C9  =  2.75573192239858907e-6f;
    constexpr float C11 = -2.50521083854417188e-8f;
    constexpr float C13 =  1.60590438368216146e-10f;

    float st = fmaf(zh, fmaf(zh, C13, C11), C9);
    float u  = fmaf(zh, st, C7);
    float m1h = zh * u;
    float m1l = fmaf(zh, u, -m1h) + zl * u;
    float Rh = C5h + m1h;
    float Rl = ((C5h - Rh) + m1h) + (m1l + C5l);
    float m2h = zh * Rh;
    float m2l = fmaf(zh, Rh, -m2h) + fmaf(zh, Rl, zl * Rh);
    float Ph = C3h + m2h;
    float Pl = ((C3h - Ph) + m2h) + (m2l + C3l);
    float wh = zh * rh;
    float wl = fmaf(zh, rh, -wh) + fmaf(zl, rh, zh * rl);
    float ch = wh * Ph;
    float cl = fmaf(wh, Ph, -ch) + fmaf(wh, Pl, wl * Ph);
    float sh = rh + ch;
    float sl = ((rh - sh) + ch) + (cl + rl);
    float sinv = sh + sl;

    // cos(r) = 1 - z/2 + z^2 * C(z)
    constexpr double c4d = 1.0 / 24.0;
    constexpr float C4h = (float)c4d, C4l = (float)(c4d - (double)C4h);
    constexpr float D6  = -1.38888888888888889e-3f;
    constexpr float D8  =  2.48015873015873016e-5f;
    constexpr float D10 = -2.75573192239858907e-7f;
    constexpr float D12 =  2.08767569878680990e-9f;

    float tt = fmaf(zh, fmaf(zh, D12, D10), D8);
    float u2 = fmaf(zh, tt, D6);
    float n1h = zh * u2;
    float n1l = fmaf(zh, u2, -n1h) + zl * u2;
    float Gh = C4h + n1h;
    float Gl = ((C4h - Gh) + n1h) + (n1l + C4l);
    float n2h = zh * Gh;
    float n2l = fmaf(zh, Gh, -n2h) + fmaf(zh, Gl, zl * Gh);
    float Hh = -0.5f + n2h;
    float Hl = ((-0.5f - Hh) + n2h) + n2l;
    float n3h = zh * Hh;
    float n3l = fmaf(zh, Hh, -n3h) + fmaf(zh, Hl, zl * Hh);
    float th = 1.0f + n3h;
    float tl = ((1.0f - th) + n3h) + n3l;
    float cosv = th + tl;

    float res = (q & 1) ? cosv : sinv;
    return (q & 2) ? -res : res;
}

__global__ __launch_bounds__(256) void siren_kernel(
    const float* __restrict__ coords,
    const float* __restrict__ weights,
    float* __restrict__ out,
    int N)
{
    __shared__ float s[PSZ];
    const int b = blockIdx.y;

    const float* wb = weights + (size_t)b * PSZ;
    for (int i = threadIdx.x; i < PSZ; i += blockDim.x) s[i] = wb[i];
    __syncthreads();

    const int n = blockIdx.x * blockDim.x + threadIdx.x;
    if (n >= N) return;

    const float2 c =
        reinterpret_cast<const float2*>(coords + (size_t)b * (size_t)N * 2)[n];

    float a0[HID];
    float a1[HID];

    // ---- Layer 1: 2 -> 20 ---- no-fma dot: round(mul) + round(mul), then add
    #pragma unroll
    for (int o = 0; o < HID; o++) {
        float acc = __fadd_rn(__fmul_rn(s[2 * o], c.x),
                              __fmul_rn(s[2 * o + 1], c.y));
        acc = __fadd_rn(acc, s[40 + o]);
        a0[o] = sin_cr(__fmul_rn(20.0f, acc));
    }

    // ---- Layer 2: 20 -> 20 ---- no-fma sequential accumulation
    #pragma unroll
    for (int o = 0; o < HID; o++) {
        float acc = 0.0f;
        #pragma unroll
        for (int i = 0; i < HID; i++)
            acc = __fadd_rn(acc, __fmul_rn(s[60 + o * HID + i], a0[i]));
        acc = __fadd_rn(acc, s[460 + o]);
        a1[o] = sin_cr(__fmul_rn(20.0f, acc));
    }

    // ---- Layer 3: 20 -> 20 ----
    #pragma unroll
    for (int o = 0; o < HID; o++) {
        float acc = 0.0f;
        #pragma unroll
        for (int i = 0; i < HID; i++)
            acc = __fadd_rn(acc, __fmul_rn(s[480 + o * HID + i], a1[i]));
        acc = __fadd_rn(acc, s[880 + o]);
        a0[o] = sin_cr(__fmul_rn(20.0f, acc));
    }

    // ---- Layer 4: 20 -> 1, clip ----
    float acc = 0.0f;
    #pragma unroll
    for (int i = 0; i < HID; i++)
        acc = __fadd_rn(acc, __fmul_rn(s[900 + i], a0[i]));
    acc = __fadd_rn(acc, s[920]);

    out[(size_t)b * (size_t)N + n] = fminf(fmaxf(acc, 0.0f), 1.0f);
}

extern "C" void kernel_launch(void* const* d_in, const int* in_sizes, int n_in,
                              void* d_out, int out_size) {
    const float* coords  = (const float*)d_in[0];   // (B, N, 2)
    const float* weights = (const float*)d_in[1];   // (B, 921)
    float* out = (float*)d_out;                     // (B, N, 1)

    const int B = in_sizes[1] / PSZ;
    const int N = in_sizes[0] / (2 * B);

    dim3 block(256);
    dim3 grid((N + 255) / 256, B);
    siren_kernel<<<grid, block>>>(coords, weights, out, N);
}

// round 6
// speedup vs baseline: 1.3857x; 1.3857x over previous
#include <cuda_runtime.h>
#include <math.h>

// Batched SIREN MLP: coords (B,N,2) f32, flat_weights (B,921) f32 -> (B,N,1) f32
// 2->20->20->20->1, hidden act sin(20*(Wx+b)), final clip [0,1].
//
// Numerics contract (established R4, PASS @ rel_err 7.54e-4):
//  - dots: UNCONTRACTED round(mul)+round(add), k ascending, acc from 0
//  - +b, *20 as separate rounded ops
//  - sine: must match the reference libm closely. Amplification budget:
//    layer-1 sine 1-ulp error -> up to ~1e-3 at output  => correctly-rounded sine
//    layer-2 sine 1-ulp error -> ~1.6e-5                => libdevice sinf is enough
//    layer-3 sine 1-ulp error -> ~4e-7                  => libdevice sinf is enough
// (R1 vs R3 showed libdevice sinf ~= correctly rounded on these args.)

#define HID 20
#define PSZ 921

__device__ __forceinline__ float sin_cr(float x) {
    // Correctly-rounded float sine for |x| <= ~1600 (float-float, abs err ~1e-11).
    constexpr float  INV_PIO2 = 0.636619772367581343f;
    constexpr float  P1 = 1.57079637050628662109375f;          // float(pi/2)
    constexpr double PIO2 = 1.5707963267948966192313216916398;
    constexpr double D1 = PIO2 - (double)P1;
    constexpr float  P2 = (float)D1;
    constexpr float  P3 = (float)(D1 - (double)P2);

    float kf = rintf(x * INV_PIO2);
    int   q  = (int)kf;

    float ph = kf * P1;
    float pl = fmaf(kf, P1, -ph);
    float s  = x - ph;
    float bb = s - x;
    float er = (x - (s - bb)) + ((-ph) - bb);
    float mh = kf * P2;
    float ml = fmaf(kf, P2, -mh);
    float lo = ((er - pl) - mh) - ml;
    lo = fmaf(-kf, P3, lo);
    float rh = s + lo;
    float rl = (s - rh) + lo;

    float zh = rh * rh;
    float zl = fmaf(2.0f * rh, rl, fmaf(rh, rh, -zh));

    constexpr double c3d = -1.0 / 6.0,  c5d = 1.0 / 120.0;
    constexpr float C3h = (float)c3d, C3l = (float)(c3d - (double)C3h);
    constexpr float C5h = (float)c5d, C5l = (float)(c5d - (double)C5h);
    constexpr float C7  = -1.98412698412698413e-4f;
    constexpr float C9  =  2.75573192239858907e-6f;
    constexpr float C11 = -2.50521083854417188e-8f;
    constexpr float C13 =  1.60590438368216146e-10f;

    float st = fmaf(zh, fmaf(zh, C13, C11), C9);
    float u  = fmaf(zh, st, C7);
    float m1h = zh * u;
    float m1l = fmaf(zh, u, -m1h) + zl * u;
    float Rh = C5h + m1h;
    float Rl = ((C5h - Rh) + m1h) + (m1l + C5l);
    float m2h = zh * Rh;
    float m2l = fmaf(zh, Rh, -m2h) + fmaf(zh, Rl, zl * Rh);
    float Ph = C3h + m2h;
    float Pl = ((C3h - Ph) + m2h) + (m2l + C3l);
    float wh = zh * rh;
    float wl = fmaf(zh, rh, -wh) + fmaf(zl, rh, zh * rl);
    float ch = wh * Ph;
    float cl = fmaf(wh, Ph, -ch) + fmaf(wh, Pl, wl * Ph);
    float sh = rh + ch;
    float sl = ((rh - sh) + ch) + (cl + rl);
    float sinv = sh + sl;

    constexpr double c4d = 1.0 / 24.0;
    constexpr float C4h = (float)c4d, C4l = (float)(c4d - (double)C4h);
    constexpr float D6  = -1.38888888888888889e-3f;
    constexpr float D8  =  2.48015873015873016e-5f;
    constexpr float D10 = -2.75573192239858907e-7f;
    constexpr float D12 =  2.08767569878680990e-9f;

    float tt = fmaf(zh, fmaf(zh, D12, D10), D8);
    float u2 = fmaf(zh, tt, D6);
    float n1h = zh * u2;
    float n1l = fmaf(zh, u2, -n1h) + zl * u2;
    float Gh = C4h + n1h;
    float Gl = ((C4h - Gh) + n1h) + (n1l + C4l);
    float n2h = zh * Gh;
    float n2l = fmaf(zh, Gh, -n2h) + fmaf(zh, Gl, zl * Gh);
    float Hh = -0.5f + n2h;
    float Hl = ((-0.5f - Hh) + n2h) + n2l;
    float n3h = zh * Hh;
    float n3l = fmaf(zh, Hh, -n3h) + fmaf(zh, Hl, zl * Hh);
    float th = 1.0f + n3h;
    float tl = ((1.0f - th) + n3h) + n3l;
    float cosv = th + tl;

    float res = (q & 1) ? cosv : sinv;
    return (q & 2) ? -res : res;
}

__global__ __launch_bounds__(256) void siren_kernel(
    const float* __restrict__ coords,
    const float* __restrict__ weights,
    float* __restrict__ out,
    int N)
{
    __shared__ float s[PSZ];
    const int b = blockIdx.y;

    const float* wb = weights + (size_t)b * PSZ;
    for (int i = threadIdx.x; i < PSZ; i += blockDim.x) s[i] = wb[i];
    __syncthreads();

    const int n = blockIdx.x * blockDim.x + threadIdx.x;
    if (n >= N) return;

    const float2 c =
        reinterpret_cast<const float2*>(coords + (size_t)b * (size_t)N * 2)[n];

    float a0[HID];
    float a1[HID];

    // ---- Layer 1: 2 -> 20 ---- no-fma dot; CORRECTLY-ROUNDED sine (critical)
    #pragma unroll
    for (int o = 0; o < HID; o++) {
        float acc = __fadd_rn(__fmul_rn(s[2 * o], c.x),
                              __fmul_rn(s[2 * o + 1], c.y));
        acc = __fadd_rn(acc, s[40 + o]);
        a0[o] = sin_cr(__fmul_rn(20.0f, acc));
    }

    // ---- Layer 2: 20 -> 20 ---- no-fma dot; libdevice sinf (ulp-noise ~1.6e-5)
    #pragma unroll
    for (int o = 0; o < HID; o++) {
        float acc = 0.0f;
        #pragma unroll
        for (int i = 0; i < HID; i++)
            acc = __fadd_rn(acc, __fmul_rn(s[60 + o * HID + i], a0[i]));
        acc = __fadd_rn(acc, s[460 + o]);
        a1[o] = sinf(__fmul_rn(20.0f, acc));
    }

    // ---- Layer 3: 20 -> 20 ---- no-fma dot; libdevice sinf (ulp-noise ~4e-7)
    #pragma unroll
    for (int o = 0; o < HID; o++) {
        float acc = 0.0f;
        #pragma unroll
        for (int i = 0; i < HID; i++)
            acc = __fadd_rn(acc, __fmul_rn(s[480 + o * HID + i], a1[i]));
        acc = __fadd_rn(acc, s[880 + o]);
        a0[o] = sinf(__fmul_rn(20.0f, acc));
    }

    // ---- Layer 4: 20 -> 1, clip ----
    float acc = 0.0f;
    #pragma unroll
    for (int i = 0; i < HID; i++)
        acc = __fadd_rn(acc, __fmul_rn(s[900 + i], a0[i]));
    acc = __fadd_rn(acc, s[920]);

    out[(size_t)b * (size_t)N + n] = fminf(fmaxf(acc, 0.0f), 1.0f);
}

extern "C" void kernel_launch(void* const* d_in, const int* in_sizes, int n_in,
                              void* d_out, int out_size) {
    const float* coords  = (const float*)d_in[0];   // (B, N, 2)
    const float* weights = (const float*)d_in[1];   // (B, 921)
    float* out = (float*)d_out;                     // (B, N, 1)

    const int B = in_sizes[1] / PSZ;
    const int N = in_sizes[0] / (2 * B);

    dim3 block(256);
    dim3 grid((N + 255) / 256, B);
    siren_kernel<<<grid, block>>>(coords, weights, out, N);
}

// round 7
// speedup vs baseline: 2.0961x; 1.5127x over previous
#include <cuda_runtime.h>
#include <math.h>

// Batched SIREN MLP: coords (B,N,2) f32, flat_weights (B,921) f32 -> (B,N,1) f32
// 2->20->20->20->1, hidden act sin(20*(Wx+b)), final clip [0,1].
//
// Numerics contract (R4/R6 evidence):
//  - dots: UNCONTRACTED round(mul)+round(add), k ascending, acc from 0
//    (FMA contraction -> 8.4e-3, fails)
//  - +b, *20 as separate rounded ops
//  - R6 showed the 7.54e-4 residual floor is insensitive to layer-2/3 sine
//    quality; hypothesis: reference is JAX-GPU whose jnp.sin lowers to
//    libdevice __nv_sinf. This round uses libdevice sinf at ALL layers to
//    test bitwise-match of layer 1 (and get ~30% faster).

#define HID 20
#define PSZ 921

__global__ __launch_bounds__(256) void siren_kernel(
    const float* __restrict__ coords,
    const float* __restrict__ weights,
    float* __restrict__ out,
    int N)
{
    __shared__ float s[PSZ];
    const int b = blockIdx.y;

    const float* wb = weights + (size_t)b * PSZ;
    for (int i = threadIdx.x; i < PSZ; i += blockDim.x) s[i] = wb[i];
    __syncthreads();

    const int n = blockIdx.x * blockDim.x + threadIdx.x;
    if (n >= N) return;

    const float2 c =
        reinterpret_cast<const float2*>(coords + (size_t)b * (size_t)N * 2)[n];

    float a0[HID];
    float a1[HID];

    // ---- Layer 1: 2 -> 20 ---- no-fma dot; libdevice sinf
    #pragma unroll
    for (int o = 0; o < HID; o++) {
        float acc = __fadd_rn(__fmul_rn(s[2 * o], c.x),
                              __fmul_rn(s[2 * o + 1], c.y));
        acc = __fadd_rn(acc, s[40 + o]);
        a0[o] = sinf(__fmul_rn(20.0f, acc));
    }

    // ---- Layer 2: 20 -> 20 ---- no-fma sequential dot; libdevice sinf
    #pragma unroll
    for (int o = 0; o < HID; o++) {
        float acc = 0.0f;
        #pragma unroll
        for (int i = 0; i < HID; i++)
            acc = __fadd_rn(acc, __fmul_rn(s[60 + o * HID + i], a0[i]));
        acc = __fadd_rn(acc, s[460 + o]);
        a1[o] = sinf(__fmul_rn(20.0f, acc));
    }

    // ---- Layer 3: 20 -> 20 ----
    #pragma unroll
    for (int o = 0; o < HID; o++) {
        float acc = 0.0f;
        #pragma unroll
        for (int i = 0; i < HID; i++)
            acc = __fadd_rn(acc, __fmul_rn(s[480 + o * HID + i], a1[i]));
        acc = __fadd_rn(acc, s[880 + o]);
        a0[o] = sinf(__fmul_rn(20.0f, acc));
    }

    // ---- Layer 4: 20 -> 1, clip ----
    float acc = 0.0f;
    #pragma unroll
    for (int i = 0; i < HID; i++)
        acc = __fadd_rn(acc, __fmul_rn(s[900 + i], a0[i]));
    acc = __fadd_rn(acc, s[920]);

    out[(size_t)b * (size_t)N + n] = fminf(fmaxf(acc, 0.0f), 1.0f);
}

extern "C" void kernel_launch(void* const* d_in, const int* in_sizes, int n_in,
                              void* d_out, int out_size) {
    const float* coords  = (const float*)d_in[0];   // (B, N, 2)
    const float* weights = (const float*)d_in[1];   // (B, 921)
    float* out = (float*)d_out;                     // (B, N, 1)

    const int B = in_sizes[1] / PSZ;
    const int N = in_sizes[0] / (2 * B);

    dim3 block(256);
    dim3 grid((N + 255) / 256, B);
    siren_kernel<<<grid, block>>>(coords, weights, out, N);
}

// round 10
// speedup vs baseline: 2.4404x; 1.1643x over previous
#include <cuda_runtime.h>
#include <math.h>

// Batched SIREN MLP: coords (B,N,2) f32, flat_weights (B,921) f32 -> (B,N,1) f32
// 2->20->20->20->1, hidden act sin(20*(Wx+b)), final clip [0,1].
//
// Numerics contract (R4-R8 evidence):
//  - dots: UNCONTRACTED round(mul)+round(add), k ascending, acc from 0 (scalar
//    FMUL/FADD only — packed f32x2 rounds differently and FAILS, see R5/R8)
//  - +b, *20 separate rounded ops
//  - sine: needs abs accuracy ~1e-8; empirical layer-1 amplification to the
//    output is only ~500x (R6 vs R7), so a branch-free Cody-Waite + Taylor
//    sine (err ~2e-8) keeps rel_err ~7.8e-4.
// This round: (1) LDS.128 vectorized weight loads (bit-exact), (2) custom sine.

#define HID 20
#define PSZ 921

// Branch-free sine, valid |x| <= ~3000 (k <= ~2000). Abs err ~2-3e-8.
__device__ __forceinline__ float sin_fast(float x) {
    constexpr float  INV_PIO2 = 0.63661977236758134308f;
    constexpr double PIO2 = 1.5707963267948966192313216916398;
    constexpr float  P1 = (float)PIO2;                          // RN(pi/2)
    constexpr float  P2 = (float)(PIO2 - (double)P1);
    constexpr float  P3 = (float)((PIO2 - (double)P1) - (double)P2);

    float kf = rintf(x * INV_PIO2);
    int   q  = (int)kf;

    float r = fmaf(-kf, P1, x);
    r = fmaf(-kf, P2, r);
    r = fmaf(-kf, P3, r);

    float z = r * r;

    // sin(r): Taylor through r^9 (trunc err ~1.8e-9 at pi/4)
    float p = fmaf(z,  2.75573192239858907e-6f, -1.98412698412698413e-4f);
    p = fmaf(z, p,  8.33333333333333322e-3f);
    p = fmaf(z, p, -1.66666666666666667e-1f);
    float sinv = fmaf(r * z, p, r);

    // cos(r): Taylor through z^5 (trunc err ~1.2e-10 at pi/4)
    float c = fmaf(z, -2.75573192239858907e-7f, 2.48015873015873016e-5f);
    c = fmaf(z, c, -1.38888888888888889e-3f);
    c = fmaf(z, c,  4.16666666666666644e-2f);
    c = fmaf(z, c, -0.5f);
    float cosv = fmaf(z, c, 1.0f);

    float v = (q & 1) ? cosv : sinv;
    return __uint_as_float(__float_as_uint(v) ^ ((unsigned)(q & 2) << 30));
}

__global__ __launch_bounds__(256) void siren_kernel(
    const float* __restrict__ coords,
    const float* __restrict__ weights,
    float* __restrict__ out,
    int N)
{
    __shared__ __align__(16) float s[PSZ];
    const int b = blockIdx.y;

    const float* wb = weights + (size_t)b * PSZ;
    for (int i = threadIdx.x; i < PSZ; i += blockDim.x) s[i] = wb[i];
    __syncthreads();

    const int n = blockIdx.x * blockDim.x + threadIdx.x;
    if (n >= N) return;

    const float2 c =
        reinterpret_cast<const float2*>(coords + (size_t)b * (size_t)N * 2)[n];

    float a0[HID];
    float a1[HID];

    // ---- Layer 1: 2 -> 20 ---- (uncontracted; LDS.64 weight pairs)
    #pragma unroll
    for (int o = 0; o < HID; o++) {
        float2 w = *reinterpret_cast<const float2*>(&s[2 * o]);
        float acc = __fadd_rn(__fmul_rn(w.x, c.x), __fmul_rn(w.y, c.y));
        acc = __fadd_rn(acc, s[40 + o]);
        a0[o] = sin_fast(__fmul_rn(20.0f, acc));
    }

    // ---- Layer 2: 20 -> 20 ---- (sequential uncontracted; LDS.128 weights)
    // Row base 60+20*o floats = 240+80*o bytes: 16B aligned.
    #pragma unroll
    for (int o = 0; o < HID; o++) {
        const float4* wrow = reinterpret_cast<const float4*>(&s[60 + o * HID]);
        float acc = 0.0f;
        #pragma unroll
        for (int v = 0; v < HID / 4; v++) {
            float4 w = wrow[v];
            acc = __fadd_rn(acc, __fmul_rn(w.x, a0[4 * v + 0]));
            acc = __fadd_rn(acc, __fmul_rn(w.y, a0[4 * v + 1]));
            acc = __fadd_rn(acc, __fmul_rn(w.z, a0[4 * v + 2]));
            acc = __fadd_rn(acc, __fmul_rn(w.w, a0[4 * v + 3]));
        }
        acc = __fadd_rn(acc, s[460 + o]);
        a1[o] = sin_fast(__fmul_rn(20.0f, acc));
    }

    // ---- Layer 3: 20 -> 20 ---- (row base 480+20*o floats: 16B aligned)
    #pragma unroll
    for (int o = 0; o < HID; o++) {
        const float4* wrow = reinterpret_cast<const float4*>(&s[480 + o * HID]);
        float acc = 0.0f;
        #pragma unroll
        for (int v = 0; v < HID / 4; v++) {
            float4 w = wrow[v];
            acc = __fadd_rn(acc, __fmul_rn(w.x, a1[4 * v + 0]));
            acc = __fadd_rn(acc, __fmul_rn(w.y, a1[4 * v + 1]));
            acc = __fadd_rn(acc, __fmul_rn(w.z, a1[4 * v + 2]));
            acc = __fadd_rn(acc, __fmul_rn(w.w, a1[4 * v + 3]));
        }
        acc = __fadd_rn(acc, s[880 + o]);
        a0[o] = sin_fast(__fmul_rn(20.0f, acc));
    }

    // ---- Layer 4: 20 -> 1, clip ---- (row base 900 floats = 3600 B: aligned)
    {
        const float4* wrow = reinterpret_cast<const float4*>(&s[900]);
        float acc = 0.0f;
        #pragma unroll
        for (int v = 0; v < HID / 4; v++) {
            float4 w = wrow[v];
            acc = __fadd_rn(acc, __fmul_rn(w.x, a0[4 * v + 0]));
            acc = __fadd_rn(acc, __fmul_rn(w.y, a0[4 * v + 1]));
            acc = __fadd_rn(acc, __fmul_rn(w.z, a0[4 * v + 2]));
            acc = __fadd_rn(acc, __fmul_rn(w.w, a0[4 * v + 3]));
        }
        acc = __fadd_rn(acc, s[920]);
        out[(size_t)b * (size_t)N + n] = fminf(fmaxf(acc, 0.0f), 1.0f);
    }
}

extern "C" void kernel_launch(void* const* d_in, const int* in_sizes, int n_in,
                              void* d_out, int out_size) {
    const float* coords  = (const float*)d_in[0];   // (B, N, 2)
    const float* weights = (const float*)d_in[1];   // (B, 921)
    float* out = (float*)d_out;                     // (B, N, 1)

    const int B = in_sizes[1] / PSZ;
    const int N = in_sizes[0] / (2 * B);

    dim3 block(256);
    dim3 grid((N + 255) / 256, B);
    siren_kernel<<<grid, block>>>(coords, weights, out, N);
}